// round 11
// baseline (speedup 1.0000x reference)
#include <cuda_runtime.h>
#include <cuda_bf16.h>
#include <math.h>
#include <stdint.h>

// ============================================================================
// CrossAttentionReader — GB300 sm_103a, round 11
//  - round-10 structure +
//  - attn rewritten: 16 rows/block, transposed-q smem, no shuffle chains,
//    per-row sign select (16x less K/V L2 traffic, same parallelism)
//  - split_Wo moved off the pre-join critical path (side B)
// ============================================================================

#define D_MAX     1024
#define M_MAX     32768
#define ROWS_MAX  2048
#define TKK       32
#define NHEADS    16

// ---- scratch (device globals; no allocation allowed) ----
__device__ float g_r[M_MAX];
__device__ float g_wbar[D_MAX];
__device__ float g_colpart[8 * D_MAX];
__device__ int   g_posidx[TKK];
__device__ int   g_negidx[TKK];
__device__ int   g_sign[ROWS_MAX];
__device__ unsigned long long g_cand[2 * 1024];
__device__ float g_projpart[8 * 4 * TKK * D_MAX];   // [mat*8+ksp][slot][o]
__device__ float g_Kp[TKK * D_MAX];
__device__ float g_Kn[TKK * D_MAX];
__device__ float g_Vp[TKK * D_MAX];
__device__ float g_Vn[TKK * D_MAX];
__device__ float g_qfull[(size_t)ROWS_MAX * D_MAX];
__device__ __nv_bfloat16 g_xhi[(size_t)ROWS_MAX * D_MAX];
__device__ __nv_bfloat16 g_xlo[(size_t)ROWS_MAX * D_MAX];
__device__ __nv_bfloat16 g_ctxhi[(size_t)ROWS_MAX * D_MAX];
__device__ __nv_bfloat16 g_ctxlo[(size_t)ROWS_MAX * D_MAX];
__device__ __nv_bfloat16 g_Wqhi[(size_t)D_MAX * D_MAX];
__device__ __nv_bfloat16 g_Wqlo[(size_t)D_MAX * D_MAX];
__device__ __nv_bfloat16 g_Wohi[(size_t)D_MAX * D_MAX];
__device__ __nv_bfloat16 g_Wolo[(size_t)D_MAX * D_MAX];

// ============================ helpers ===================================
__device__ __forceinline__ uint32_t smem_u32(const void* p) {
    uint32_t a;
    asm("{ .reg .u64 t; cvta.to.shared.u64 t, %1; cvt.u32.u64 %0, t; }" : "=r"(a) : "l"(p));
    return a;
}
__device__ __forceinline__ void ldsm_x4(uint32_t* r, uint32_t addr) {
    asm volatile("ldmatrix.sync.aligned.m8n8.x4.shared.b16 {%0,%1,%2,%3}, [%4];"
                 : "=r"(r[0]), "=r"(r[1]), "=r"(r[2]), "=r"(r[3]) : "r"(addr));
}
__device__ __forceinline__ void mma_bf16(float* d, const uint32_t* a, const uint32_t* b) {
    asm volatile("mma.sync.aligned.m16n8k16.row.col.f32.bf16.bf16.f32 "
                 "{%0,%1,%2,%3}, {%4,%5,%6,%7}, {%8,%9}, {%0,%1,%2,%3};"
                 : "+f"(d[0]), "+f"(d[1]), "+f"(d[2]), "+f"(d[3])
                 : "r"(a[0]), "r"(a[1]), "r"(a[2]), "r"(a[3]), "r"(b[0]), "r"(b[1]));
}
#define CP_ASYNC16(sa, gp) \
    asm volatile("cp.async.cg.shared.global [%0], [%1], 16;" :: "r"(sa), "l"(gp))
#define CP_COMMIT() asm volatile("cp.async.commit_group;" ::: "memory")
#define CP_WAIT(n)  asm volatile("cp.async.wait_group %0;" :: "n"(n) : "memory")

// ---------------------------------------------------------------------------
// split fp32 -> bf16 hi/lo
// ---------------------------------------------------------------------------
__global__ void split_kernel(const float* __restrict__ src, __nv_bfloat16* __restrict__ hi,
                             __nv_bfloat16* __restrict__ lo, int n4) {
    int i = blockIdx.x * 256 + threadIdx.x;
    if (i >= n4) return;
    float4 v = ((const float4*)src)[i];
    __nv_bfloat16 h0 = __float2bfloat16(v.x), h1 = __float2bfloat16(v.y);
    __nv_bfloat16 h2 = __float2bfloat16(v.z), h3 = __float2bfloat16(v.w);
    __nv_bfloat16 l0 = __float2bfloat16(v.x - __bfloat162float(h0));
    __nv_bfloat16 l1 = __float2bfloat16(v.y - __bfloat162float(h1));
    __nv_bfloat16 l2 = __float2bfloat16(v.z - __bfloat162float(h2));
    __nv_bfloat16 l3 = __float2bfloat16(v.w - __bfloat162float(h3));
    ((__nv_bfloat162*)hi)[2 * i]     = __nv_bfloat162(h0, h1);
    ((__nv_bfloat162*)hi)[2 * i + 1] = __nv_bfloat162(h2, h3);
    ((__nv_bfloat162*)lo)[2 * i]     = __nv_bfloat162(l0, l1);
    ((__nv_bfloat162*)lo)[2 * i + 1] = __nv_bfloat162(l2, l3);
}

// ---------------------------------------------------------------------------
// column sum of Wq — two-stage deterministic reduction
// ---------------------------------------------------------------------------
__global__ void colsum1_kernel(const float* __restrict__ W, float* __restrict__ part, int D) {
    int d = blockIdx.x * 256 + threadIdx.x;
    if (d >= D) return;
    int r0 = blockIdx.y * 128;
    float s = 0.f;
    for (int r = r0; r < r0 + 128; r++) s += W[(size_t)r * D + d];
    part[blockIdx.y * D + d] = s;
}
__global__ void colsum2_kernel(const float* __restrict__ part, float* __restrict__ wbar, int D) {
    int d = blockIdx.x * 256 + threadIdx.x;
    if (d >= D) return;
    float s = 0.f;
    #pragma unroll
    for (int i = 0; i < 8; i++) s += part[i * D + d];
    wbar[d] = s;
}

// ---------------------------------------------------------------------------
// per-row r[m] = sum / (sqrtD * norm)
// ---------------------------------------------------------------------------
__global__ void rowstat_kernel(const float* __restrict__ mk, float* __restrict__ r,
                               int M, int D, float sqrtD) {
    int warp = threadIdx.x >> 5, lane = threadIdx.x & 31;
    int m = blockIdx.x * 8 + warp;
    if (m >= M) return;
    const float* row = mk + (size_t)m * D;
    float s = 0.f, ss = 0.f;
    for (int j = lane * 4; j < D; j += 128) {
        float4 v = *(const float4*)(row + j);
        s  += v.x + v.y + v.z + v.w;
        ss += v.x * v.x + v.y * v.y + v.z * v.z + v.w * v.w;
    }
    #pragma unroll
    for (int off = 16; off; off >>= 1) {
        s  += __shfl_xor_sync(0xffffffffu, s, off);
        ss += __shfl_xor_sync(0xffffffffu, ss, off);
    }
    if (lane == 0) r[m] = s / (sqrtD * sqrtf(ss));
}

// ---------------------------------------------------------------------------
// sign(qm) per row
// ---------------------------------------------------------------------------
__global__ void qmsign_kernel(const float* __restrict__ x, const float* __restrict__ wbar,
                              int* __restrict__ sgn, int rows, int D) {
    int warp = threadIdx.x >> 5, lane = threadIdx.x & 31;
    int rn = blockIdx.x * 8 + warp;
    if (rn >= rows) return;
    const float* row = x + (size_t)rn * D;
    float s = 0.f;
    for (int j = lane * 4; j < D; j += 128) {
        float4 v = *(const float4*)(row + j);
        float4 w = *(const float4*)(wbar + j);
        s += v.x * w.x + v.y * w.y + v.z * w.z + v.w * w.w;
    }
    #pragma unroll
    for (int off = 16; off; off >>= 1) s += __shfl_xor_sync(0xffffffffu, s, off);
    if (lane == 0) sgn[rn] = (s >= 0.f) ? 1 : 0;
}

// ---------------------------------------------------------------------------
// topk: 2-stage bitonic. key = (orderable(value) << 32) | ~idx
// ---------------------------------------------------------------------------
__device__ __forceinline__ void bitonic_desc_1024(unsigned long long* s, int tid) {
    for (int k = 2; k <= 1024; k <<= 1) {
        for (int j = k >> 1; j > 0; j >>= 1) {
            int l = tid ^ j;
            if (l > tid) {
                unsigned long long a = s[tid], b = s[l];
                bool desc = ((tid & k) == 0);
                bool sw = desc ? (a < b) : (a > b);
                if (sw) { s[tid] = b; s[l] = a; }
            }
            __syncthreads();
        }
    }
}

__global__ void topk_stage1(const float* __restrict__ r, int M,
                            unsigned long long* __restrict__ cand) {
    int mode = blockIdx.y, seg = blockIdx.x, tid = threadIdx.x;
    __shared__ unsigned long long s[1024];
    int gi = seg * 1024 + tid;
    unsigned long long key = 0ull;
    if (gi < M) {
        uint32_t b = __float_as_uint(r[gi]);
        uint32_t u = (b & 0x80000000u) ? ~b : (b | 0x80000000u);
        if (mode) u = ~u;
        key = ((unsigned long long)u << 32) | (uint32_t)(~gi);
    }
    s[tid] = key;
    __syncthreads();
    bitonic_desc_1024(s, tid);
    if (tid < 32) cand[mode * 1024 + seg * 32 + tid] = s[tid];
}

__global__ void topk_stage2(const unsigned long long* __restrict__ cand, int ncand,
                            int* __restrict__ pos, int* __restrict__ neg) {
    int mode = blockIdx.x, tid = threadIdx.x;
    __shared__ unsigned long long s[1024];
    s[tid] = (tid < ncand) ? cand[mode * 1024 + tid] : 0ull;
    __syncthreads();
    bitonic_desc_1024(s, tid);
    if (tid < 32) {
        int idx = (int)(~(uint32_t)(s[tid] & 0xffffffffu));
        (mode ? neg : pos)[tid] = idx;
    }
}

// ---------------------------------------------------------------------------
// proj stage 1: K-split partials; grid (D/128, 4, 8); block 256
// ---------------------------------------------------------------------------
__global__ void __launch_bounds__(256) proj1_kernel(
        const float* __restrict__ mk, const float* __restrict__ mv,
        const float* __restrict__ Wk, const float* __restrict__ Wv,
        const int* __restrict__ pos, const int* __restrict__ neg,
        float* __restrict__ part, int D) {
    int mat = blockIdx.y, ksp = blockIdx.z;
    const float* src = (mat < 2) ? mk : mv;
    const float* W   = (mat < 2) ? Wk : Wv;
    const int*   idx = (mat & 1) ? neg : pos;
    float* outp = part + ((size_t)(mat * 8 + ksp)) * TKK * D_MAX;

    int o0 = blockIdx.x * 128;
    int kbase = ksp * 128;
    __shared__ float Ks[32][36];
    __shared__ float Ws[32][132];
    __shared__ int   sidx[32];
    int tid = threadIdx.x;
    if (tid < 32) sidx[tid] = idx[tid];
    __syncthreads();

    int tx = tid & 31, ty = tid >> 5;
    float acc[4][4] = {};
    for (int k0 = kbase; k0 < kbase + 128; k0 += 32) {
        {
            int slot = tid >> 3; int d4 = (tid & 7) * 4;
            float4 v = *(const float4*)(src + (size_t)sidx[slot] * D + k0 + d4);
            Ks[d4 + 0][slot] = v.x; Ks[d4 + 1][slot] = v.y;
            Ks[d4 + 2][slot] = v.z; Ks[d4 + 3][slot] = v.w;
        }
        #pragma unroll
        for (int q = 0; q < 4; q++) {
            int l = tid + q * 256; int row = l >> 3; int d4 = (l & 7) * 4;
            float4 v = *(const float4*)(W + (size_t)(o0 + row) * D + k0 + d4);
            Ws[d4 + 0][row] = v.x; Ws[d4 + 1][row] = v.y;
            Ws[d4 + 2][row] = v.z; Ws[d4 + 3][row] = v.w;
        }
        __syncthreads();
        #pragma unroll
        for (int kk = 0; kk < 32; kk++) {
            float a[4], b[4];
            #pragma unroll
            for (int i = 0; i < 4; i++) a[i] = Ks[kk][ty * 4 + i];
            #pragma unroll
            for (int j = 0; j < 4; j++) b[j] = Ws[kk][tx * 4 + j];
            #pragma unroll
            for (int i = 0; i < 4; i++)
                #pragma unroll
                for (int j = 0; j < 4; j++) acc[i][j] += a[i] * b[j];
        }
        __syncthreads();
    }
    #pragma unroll
    for (int i = 0; i < 4; i++)
        #pragma unroll
        for (int j = 0; j < 4; j++)
            outp[(size_t)(ty * 4 + i) * D_MAX + o0 + tx * 4 + j] = acc[i][j];
}

// ---------------------------------------------------------------------------
// proj stage 2: combine 8 K-partials (fixed order -> deterministic)
// ---------------------------------------------------------------------------
__global__ void proj2_kernel(const float* __restrict__ part,
                             float* __restrict__ Kp, float* __restrict__ Kn,
                             float* __restrict__ Vp, float* __restrict__ Vn, int D) {
    int idx = blockIdx.x * 256 + threadIdx.x;
    int mat = idx >> 15;
    int rem = idx & 32767;
    float s = 0.f;
    #pragma unroll
    for (int ksp = 0; ksp < 8; ksp++)
        s += part[((size_t)(mat * 8 + ksp)) * TKK * D_MAX + rem];
    float* outm = (mat == 0) ? Kp : (mat == 1) ? Kn : (mat == 2) ? Vp : Vn;
    outm[rem] = s;
}

// ---------------------------------------------------------------------------
// HMMA bf16 split-precision GEMM (round-6 best config).
// ---------------------------------------------------------------------------
#define STR 80
#define OAhi 0
#define OAlo 10240
#define OBhi 20480
#define OBlo 30720
#define BUFB 40960
#define GEMM_DSMEM (3 * BUFB)

__global__ void __launch_bounds__(512) gemm_hmma_kernel(
        const __nv_bfloat16* __restrict__ Ahi, const __nv_bfloat16* __restrict__ Alo,
        const __nv_bfloat16* __restrict__ Bhi, const __nv_bfloat16* __restrict__ Blo,
        const float* __restrict__ bias, float* __restrict__ C, int Kd, int Nc) {
    extern __shared__ __align__(16) uint8_t dsm[];
    int tid = threadIdx.x, wid = tid >> 5, lane = tid & 31;
    int m0g = blockIdx.y * 128, n0g = blockIdx.x * 128;
    int m0w = (wid & 3) * 32, n0w = (wid >> 2) * 32;
    uint32_t sbase = smem_u32(dsm);
    uint32_t a_off = (lane % 16) * STR + (lane / 16) * 16;
    uint32_t b_off = ((lane & 7) + ((lane >> 4) << 3)) * STR + ((lane >> 3) & 1) * 16;
    float acc[2][4][4] = {};

    int nchunk = Kd / 32;
    int lrow = tid >> 2, lseg = tid & 3;
    uint32_t lso = lrow * STR + lseg * 16;
    auto load_chunk = [&](int c, int sel) {
        uint32_t bb = sbase + sel * BUFB;
        int k0 = c * 32;
        size_t ga = (size_t)(m0g + lrow) * Kd + k0 + lseg * 8;
        size_t gb = (size_t)(n0g + lrow) * Kd + k0 + lseg * 8;
        CP_ASYNC16(bb + OAhi + lso, Ahi + ga);
        CP_ASYNC16(bb + OAlo + lso, Alo + ga);
        CP_ASYNC16(bb + OBhi + lso, Bhi + gb);
        CP_ASYNC16(bb + OBlo + lso, Blo + gb);
    };

    load_chunk(0, 0); CP_COMMIT();
    load_chunk(1, 1); CP_COMMIT();

    for (int c = 0; c < nchunk; c++) {
        CP_WAIT(1);
        __syncthreads();
        if (c + 2 < nchunk) load_chunk(c + 2, (c + 2) % 3);
        CP_COMMIT();

        uint32_t bb = sbase + (c % 3) * BUFB;
        #pragma unroll
        for (int ks = 0; ks < 2; ks++) {
            uint32_t ahi[2][4], alo[2][4], bhi[2][4], blo[2][4];
            #pragma unroll
            for (int mf = 0; mf < 2; mf++) {
                uint32_t aaddr = bb + OAhi + (m0w + mf * 16) * STR + ks * 32 + a_off;
                ldsm_x4(ahi[mf], aaddr);
                ldsm_x4(alo[mf], aaddr + (OAlo - OAhi));
            }
            #pragma unroll
            for (int ng = 0; ng < 2; ng++) {
                uint32_t baddr = bb + OBhi + (n0w + ng * 16) * STR + ks * 32 + b_off;
                ldsm_x4(bhi[ng], baddr);
                ldsm_x4(blo[ng], baddr + (OBlo - OBhi));
            }
            #pragma unroll
            for (int mf = 0; mf < 2; mf++)
                #pragma unroll
                for (int nf = 0; nf < 4; nf++)
                    mma_bf16(acc[mf][nf], ahi[mf], &bhi[nf >> 1][(nf & 1) * 2]);
            #pragma unroll
            for (int mf = 0; mf < 2; mf++)
                #pragma unroll
                for (int nf = 0; nf < 4; nf++)
                    mma_bf16(acc[mf][nf], ahi[mf], &blo[nf >> 1][(nf & 1) * 2]);
            #pragma unroll
            for (int mf = 0; mf < 2; mf++)
                #pragma unroll
                for (int nf = 0; nf < 4; nf++)
                    mma_bf16(acc[mf][nf], alo[mf], &bhi[nf >> 1][(nf & 1) * 2]);
        }
    }

    #pragma unroll
    for (int mf = 0; mf < 2; mf++)
        #pragma unroll
        for (int nf = 0; nf < 4; nf++) {
            int col = n0g + n0w + nf * 8 + (lane & 3) * 2;
            float b0 = bias ? bias[col]     : 0.f;
            float b1 = bias ? bias[col + 1] : 0.f;
            int r0 = m0g + m0w + mf * 16 + (lane >> 2);
            float2 v0 = {acc[mf][nf][0] + b0, acc[mf][nf][1] + b1};
            float2 v1 = {acc[mf][nf][2] + b0, acc[mf][nf][3] + b1};
            *(float2*)(C + (size_t)r0 * Nc + col)       = v0;
            *(float2*)(C + (size_t)(r0 + 8) * Nc + col) = v1;
        }
}

// ---------------------------------------------------------------------------
// attention v2: 16 rows per block, 512 threads, transposed-q smem.
// No shuffle reductions in scores; per-row sign via base-pointer/SEL.
// smem: qsT[1024][17] + scT[512][17]  (pad 17 -> conflict-free strided reads)
// ---------------------------------------------------------------------------
#define ATTN_ROWS 16
#define QP 17
#define ATTN_SMEM ((1024 * QP + 512 * QP) * 4)

__global__ void __launch_bounds__(512) attn_kernel(
        const float* __restrict__ qfull,
        const float* __restrict__ Kp, const float* __restrict__ Kn,
        const float* __restrict__ Vp, const float* __restrict__ Vn,
        const int* __restrict__ pos, const int* __restrict__ neg,
        const int* __restrict__ sgn,
        __nv_bfloat16* __restrict__ ctxhi, __nv_bfloat16* __restrict__ ctxlo,
        float* __restrict__ avg_out, float* __restrict__ sel_out,
        int D, float scale) {
    extern __shared__ float sm[];
    float* qsT = sm;                 // [1024][QP]
    float* scT = sm + 1024 * QP;     // [512][QP]
    __shared__ int ssgn[ATTN_ROWS];

    int tid = threadIdx.x, warp = tid >> 5, lane = tid & 31;
    int rb = blockIdx.x * ATTN_ROWS;

    if (tid < ATTN_ROWS) ssgn[tid] = sgn[rb + tid];

    // fill qsT: warp w handles row w (16 warps == 16 rows); lane covers d
    {
        int r = warp;
        const float* qrow = qfull + (size_t)(rb + r) * D;
        #pragma unroll
        for (int j = 0; j < 8; j++) {
            int d = lane * 4 + j * 128;
            float4 v = *(const float4*)(qrow + d);
            qsT[(d + 0) * QP + r] = v.x;
            qsT[(d + 1) * QP + r] = v.y;
            qsT[(d + 2) * QP + r] = v.z;
            qsT[(d + 3) * QP + r] = v.w;
        }
    }
    __syncthreads();

    // scores: warp handles 2 pairs x 16 rows; lane = (half, row)
    {
        int half = lane >> 4, rr = lane & 15;
        const float* Kb = ssgn[rr] ? Kp : Kn;
        for (int g = warp; g < 256; g += 16) {
            int p = g * 2 + half;
            int h = g >> 4;                  // same for both halves
            int k = p & 31;
            const float* kr = Kb + (size_t)k * D + h * 64;
            const float* qc = qsT + (h * 64) * QP + rr;
            float acc = 0.f;
            #pragma unroll
            for (int d = 0; d < 64; d++)
                acc = fmaf(kr[d], qc[d * QP], acc);
            scT[p * QP + rr] = acc * scale;
        }
    }
    __syncthreads();

    // softmax: warp per (r,h) task; lane = k
    for (int t = warp; t < ATTN_ROWS * NHEADS; t += 16) {
        int r = t & (ATTN_ROWS - 1), h = t / ATTN_ROWS;
        float v = scT[(h * 32 + lane) * QP + r];
        float mx = v;
        #pragma unroll
        for (int off = 16; off; off >>= 1) mx = fmaxf(mx, __shfl_xor_sync(0xffffffffu, mx, off));
        float e = expf(v - mx);
        float s = e;
        #pragma unroll
        for (int off = 16; off; off >>= 1) s += __shfl_xor_sync(0xffffffffu, s, off);
        scT[(h * 32 + lane) * QP + r] = e / s;
    }
    __syncthreads();

    // avg + sel: thread per (r,k)
    if (tid < ATTN_ROWS * TKK) {
        int r = tid >> 5, k = tid & 31;
        if (avg_out) {
            float a = 0.f;
            #pragma unroll
            for (int h = 0; h < NHEADS; h++) a += scT[(h * 32 + k) * QP + r];
            avg_out[(size_t)(rb + r) * TKK + k] = a * (1.f / NHEADS);
        }
        if (sel_out)
            sel_out[(size_t)(rb + r) * TKK + k] = (float)(ssgn[r] ? pos[k] : neg[k]);
    }

    // ctx: warp per 32-o chunk; lane = o; 16 row-accumulators
    {
        uint32_t smask = 0;
        #pragma unroll
        for (int r = 0; r < ATTN_ROWS; r++) smask |= (ssgn[r] ? 1u : 0u) << r;

        for (int ch = warp; ch < 32; ch += 16) {
            int o = ch * 32 + lane;
            int h = o >> 6;
            float acc[ATTN_ROWS];
            #pragma unroll
            for (int r = 0; r < ATTN_ROWS; r++) acc[r] = 0.f;
            for (int k = 0; k < TKK; k++) {
                float vp = Vp[(size_t)k * D + o];
                float vn = Vn[(size_t)k * D + o];
                const float* srow = scT + (h * 32 + k) * QP;
                #pragma unroll
                for (int r = 0; r < ATTN_ROWS; r++) {
                    float vv = ((smask >> r) & 1u) ? vp : vn;
                    acc[r] = fmaf(srow[r], vv, acc[r]);
                }
            }
            #pragma unroll
            for (int r = 0; r < ATTN_ROWS; r++) {
                float a = acc[r];
                __nv_bfloat16 hi = __float2bfloat16(a);
                __nv_bfloat16 lo = __float2bfloat16(a - __bfloat162float(hi));
                size_t off = (size_t)(rb + r) * D + o;
                ctxhi[off] = hi;
                ctxlo[off] = lo;
            }
        }
    }
}

// ---------------------------------------------------------------------------
// LayerNorm in-place per row
// ---------------------------------------------------------------------------
__global__ void __launch_bounds__(256) ln_kernel(
        float* __restrict__ out, const float* __restrict__ gamma,
        const float* __restrict__ beta, int D, float eps) {
    int rn = blockIdx.x;
    float* row = out + (size_t)rn * D;
    int tid = threadIdx.x;
    int warp = tid >> 5, lane = tid & 31;
    __shared__ float ssum[8], ssq[8];

    float s = 0.f, ss = 0.f;
    for (int j = tid * 4; j < D; j += 1024) {
        float4 v = *(const float4*)(row + j);
        s  += v.x + v.y + v.z + v.w;
        ss += v.x * v.x + v.y * v.y + v.z * v.z + v.w * v.w;
    }
    #pragma unroll
    for (int off = 16; off; off >>= 1) {
        s  += __shfl_xor_sync(0xffffffffu, s, off);
        ss += __shfl_xor_sync(0xffffffffu, ss, off);
    }
    if (lane == 0) { ssum[warp] = s; ssq[warp] = ss; }
    __syncthreads();
    if (tid == 0) {
        float ts = 0.f, tq = 0.f;
        #pragma unroll
        for (int w = 0; w < 8; w++) { ts += ssum[w]; tq += ssq[w]; }
        ssum[0] = ts; ssq[0] = tq;
    }
    __syncthreads();
    float mu = ssum[0] / D;
    float var = ssq[0] / D - mu * mu;
    float rstd = rsqrtf(var + eps);
    for (int j = tid * 4; j < D; j += 1024) {
        float4 v = *(const float4*)(row + j);
        float4 g = *(const float4*)(gamma + j);
        float4 bb = *(const float4*)(beta + j);
        v.x = (v.x - mu) * rstd * g.x + bb.x;
        v.y = (v.y - mu) * rstd * g.y + bb.y;
        v.z = (v.z - mu) * rstd * g.z + bb.z;
        v.w = (v.w - mu) * rstd * g.w + bb.w;
        *(float4*)(row + j) = v;
    }
}

// ---------------------------------------------------------------------------
// launch — forked graph
// ---------------------------------------------------------------------------
extern "C" void kernel_launch(void* const* d_in, const int* in_sizes, int n_in,
                              void* d_out, int out_size) {
    const float* x     = (const float*)d_in[0];
    const float* mk    = (const float*)d_in[1];
    const float* mv    = (const float*)d_in[2];
    const float* Wq    = (const float*)d_in[3];
    const float* Wk    = (const float*)d_in[4];
    const float* Wv    = (const float*)d_in[5];
    const float* Wo    = (const float*)d_in[6];
    const float* bo    = (const float*)d_in[7];
    const float* gamma = (const float*)d_in[8];
    const float* beta  = (const float*)d_in[9];

    int D    = in_sizes[7];
    int rows = in_sizes[0] / D;           // B*N
    int M    = in_sizes[1] / D;
    int hd   = D / NHEADS;

    float* out = (float*)d_out;
    float* avg_out = nullptr;
    float* sel_out = nullptr;
    if ((long long)out_size >= (long long)rows * (D + 2 * TKK)) {
        avg_out = out + (size_t)rows * D;
        sel_out = avg_out + (size_t)rows * TKK;
    }

    float *p_r, *p_wbar, *p_part, *p_ppart, *p_Kp, *p_Kn, *p_Vp, *p_Vn, *p_qf;
    int *p_pos, *p_neg, *p_sgn;
    unsigned long long* p_cand;
    __nv_bfloat16 *p_xhi, *p_xlo, *p_chi, *p_clo, *p_Wqhi, *p_Wqlo, *p_Wohi, *p_Wolo;
    cudaGetSymbolAddress((void**)&p_r,    g_r);
    cudaGetSymbolAddress((void**)&p_wbar, g_wbar);
    cudaGetSymbolAddress((void**)&p_part, g_colpart);
    cudaGetSymbolAddress((void**)&p_ppart, g_projpart);
    cudaGetSymbolAddress((void**)&p_pos,  g_posidx);
    cudaGetSymbolAddress((void**)&p_neg,  g_negidx);
    cudaGetSymbolAddress((void**)&p_sgn,  g_sign);
    cudaGetSymbolAddress((void**)&p_cand, g_cand);
    cudaGetSymbolAddress((void**)&p_Kp,   g_Kp);
    cudaGetSymbolAddress((void**)&p_Kn,   g_Kn);
    cudaGetSymbolAddress((void**)&p_Vp,   g_Vp);
    cudaGetSymbolAddress((void**)&p_Vn,   g_Vn);
    cudaGetSymbolAddress((void**)&p_qf,   g_qfull);
    cudaGetSymbolAddress((void**)&p_xhi,  g_xhi);
    cudaGetSymbolAddress((void**)&p_xlo,  g_xlo);
    cudaGetSymbolAddress((void**)&p_chi,  g_ctxhi);
    cudaGetSymbolAddress((void**)&p_clo,  g_ctxlo);
    cudaGetSymbolAddress((void**)&p_Wqhi, g_Wqhi);
    cudaGetSymbolAddress((void**)&p_Wqlo, g_Wqlo);
    cudaGetSymbolAddress((void**)&p_Wohi, g_Wohi);
    cudaGetSymbolAddress((void**)&p_Wolo, g_Wolo);

    cudaFuncSetAttribute(gemm_hmma_kernel, cudaFuncAttributeMaxDynamicSharedMemorySize,
                         GEMM_DSMEM);
    cudaFuncSetAttribute(attn_kernel, cudaFuncAttributeMaxDynamicSharedMemorySize,
                         ATTN_SMEM);

    static cudaStream_t sA = nullptr, sB = nullptr;
    static cudaEvent_t e0 = nullptr, eA = nullptr, eB = nullptr;
    if (!sA) {
        cudaStreamCreateWithFlags(&sA, cudaStreamNonBlocking);
        cudaStreamCreateWithFlags(&sB, cudaStreamNonBlocking);
        cudaEventCreateWithFlags(&e0, cudaEventDisableTiming);
        cudaEventCreateWithFlags(&eA, cudaEventDisableTiming);
        cudaEventCreateWithFlags(&eB, cudaEventDisableTiming);
    }

    float sqrtD = sqrtf((float)D);
    float scale = 1.f / sqrtf((float)hd);
    int nx4 = rows * D / 4, nw4 = D * D / 4;
    int segs = (M + 1023) / 1024;

    // ---- fork ----
    cudaEventRecord(e0, 0);
    cudaStreamWaitEvent(sA, e0, 0);
    cudaStreamWaitEvent(sB, e0, 0);

    // side A: rowstat -> topk -> proj1 -> proj2
    rowstat_kernel<<<(M + 7) / 8, 256, 0, sA>>>(mk, p_r, M, D, sqrtD);
    topk_stage1<<<dim3(segs, 2), 1024, 0, sA>>>(p_r, M, p_cand);
    topk_stage2<<<2, 1024, 0, sA>>>(p_cand, segs * 32, p_pos, p_neg);
    proj1_kernel<<<dim3(D / 128, 4, 8), 256, 0, sA>>>(mk, mv, Wk, Wv, p_pos, p_neg,
                                                      p_ppart, D);
    proj2_kernel<<<(4 * TKK * D_MAX) / 256, 256, 0, sA>>>(p_ppart, p_Kp, p_Kn,
                                                          p_Vp, p_Vn, D);
    cudaEventRecord(eA, sA);

    // side B: colsum -> qmsign, and Wo split (only needed before gemm2)
    colsum1_kernel<<<dim3((D + 255) / 256, 8), 256, 0, sB>>>(Wq, p_part, D);
    colsum2_kernel<<<(D + 255) / 256, 256, 0, sB>>>(p_part, p_wbar, D);
    qmsign_kernel<<<(rows + 7) / 8, 256, 0, sB>>>(x, p_wbar, p_sgn, rows, D);
    split_kernel<<<(nw4 + 255) / 256, 256, 0, sB>>>(Wo, p_Wohi, p_Wolo, nw4);
    cudaEventRecord(eB, sB);

    // main: x/Wq splits -> gemm1
    split_kernel<<<(nx4 + 255) / 256, 256>>>(x,  p_xhi,  p_xlo,  nx4);
    split_kernel<<<(nw4 + 255) / 256, 256>>>(Wq, p_Wqhi, p_Wqlo, nw4);
    gemm_hmma_kernel<<<dim3(D / 128, rows / 128), 512, GEMM_DSMEM>>>(
        p_xhi, p_xlo, p_Wqhi, p_Wqlo, nullptr, p_qf, D, D);

    // ---- join ----
    cudaStreamWaitEvent(0, eA, 0);
    cudaStreamWaitEvent(0, eB, 0);

    attn_kernel<<<rows / ATTN_ROWS, 512, ATTN_SMEM>>>(
        p_qf, p_Kp, p_Kn, p_Vp, p_Vn, p_pos, p_neg, p_sgn,
        p_chi, p_clo, avg_out, sel_out, D, scale);

    gemm_hmma_kernel<<<dim3(D / 128, rows / 128), 512, GEMM_DSMEM>>>(
        p_chi, p_clo, p_Wohi, p_Wolo, bo, out, D, D);

    ln_kernel<<<rows, 256>>>(out, gamma, beta, D, 1e-5f);
}

// round 12
// speedup vs baseline: 1.0769x; 1.0769x over previous
#include <cuda_runtime.h>
#include <cuda_bf16.h>
#include <math.h>
#include <stdint.h>

// ============================================================================
// CrossAttentionReader — GB300 sm_103a, round 12
//  - base: round-10 (best, 225.4us)
//  - split_Wo moved to side B (off pre-join critical path)
//  - proj1 K-split 8 -> 16 (latency-bound kernel, more CTAs)
// ============================================================================

#define D_MAX     1024
#define M_MAX     32768
#define ROWS_MAX  2048
#define TKK       32
#define NHEADS    16
#define KSPLIT    16

// ---- scratch (device globals; no allocation allowed) ----
__device__ float g_r[M_MAX];
__device__ float g_wbar[D_MAX];
__device__ float g_colpart[8 * D_MAX];
__device__ int   g_posidx[TKK];
__device__ int   g_negidx[TKK];
__device__ int   g_sign[ROWS_MAX];
__device__ unsigned long long g_cand[2 * 1024];
__device__ float g_projpart[KSPLIT * 4 * TKK * D_MAX];   // [mat*KSPLIT+ksp][slot][o]
__device__ float g_Kp[TKK * D_MAX];
__device__ float g_Kn[TKK * D_MAX];
__device__ float g_Vp[TKK * D_MAX];
__device__ float g_Vn[TKK * D_MAX];
__device__ float g_qfull[(size_t)ROWS_MAX * D_MAX];
__device__ __nv_bfloat16 g_xhi[(size_t)ROWS_MAX * D_MAX];
__device__ __nv_bfloat16 g_xlo[(size_t)ROWS_MAX * D_MAX];
__device__ __nv_bfloat16 g_ctxhi[(size_t)ROWS_MAX * D_MAX];
__device__ __nv_bfloat16 g_ctxlo[(size_t)ROWS_MAX * D_MAX];
__device__ __nv_bfloat16 g_Wqhi[(size_t)D_MAX * D_MAX];
__device__ __nv_bfloat16 g_Wqlo[(size_t)D_MAX * D_MAX];
__device__ __nv_bfloat16 g_Wohi[(size_t)D_MAX * D_MAX];
__device__ __nv_bfloat16 g_Wolo[(size_t)D_MAX * D_MAX];

// ============================ helpers ===================================
__device__ __forceinline__ uint32_t smem_u32(const void* p) {
    uint32_t a;
    asm("{ .reg .u64 t; cvta.to.shared.u64 t, %1; cvt.u32.u64 %0, t; }" : "=r"(a) : "l"(p));
    return a;
}
__device__ __forceinline__ void ldsm_x4(uint32_t* r, uint32_t addr) {
    asm volatile("ldmatrix.sync.aligned.m8n8.x4.shared.b16 {%0,%1,%2,%3}, [%4];"
                 : "=r"(r[0]), "=r"(r[1]), "=r"(r[2]), "=r"(r[3]) : "r"(addr));
}
__device__ __forceinline__ void mma_bf16(float* d, const uint32_t* a, const uint32_t* b) {
    asm volatile("mma.sync.aligned.m16n8k16.row.col.f32.bf16.bf16.f32 "
                 "{%0,%1,%2,%3}, {%4,%5,%6,%7}, {%8,%9}, {%0,%1,%2,%3};"
                 : "+f"(d[0]), "+f"(d[1]), "+f"(d[2]), "+f"(d[3])
                 : "r"(a[0]), "r"(a[1]), "r"(a[2]), "r"(a[3]), "r"(b[0]), "r"(b[1]));
}
#define CP_ASYNC16(sa, gp) \
    asm volatile("cp.async.cg.shared.global [%0], [%1], 16;" :: "r"(sa), "l"(gp))
#define CP_COMMIT() asm volatile("cp.async.commit_group;" ::: "memory")
#define CP_WAIT(n)  asm volatile("cp.async.wait_group %0;" :: "n"(n) : "memory")

// ---------------------------------------------------------------------------
// split fp32 -> bf16 hi/lo
// ---------------------------------------------------------------------------
__global__ void split_kernel(const float* __restrict__ src, __nv_bfloat16* __restrict__ hi,
                             __nv_bfloat16* __restrict__ lo, int n4) {
    int i = blockIdx.x * 256 + threadIdx.x;
    if (i >= n4) return;
    float4 v = ((const float4*)src)[i];
    __nv_bfloat16 h0 = __float2bfloat16(v.x), h1 = __float2bfloat16(v.y);
    __nv_bfloat16 h2 = __float2bfloat16(v.z), h3 = __float2bfloat16(v.w);
    __nv_bfloat16 l0 = __float2bfloat16(v.x - __bfloat162float(h0));
    __nv_bfloat16 l1 = __float2bfloat16(v.y - __bfloat162float(h1));
    __nv_bfloat16 l2 = __float2bfloat16(v.z - __bfloat162float(h2));
    __nv_bfloat16 l3 = __float2bfloat16(v.w - __bfloat162float(h3));
    ((__nv_bfloat162*)hi)[2 * i]     = __nv_bfloat162(h0, h1);
    ((__nv_bfloat162*)hi)[2 * i + 1] = __nv_bfloat162(h2, h3);
    ((__nv_bfloat162*)lo)[2 * i]     = __nv_bfloat162(l0, l1);
    ((__nv_bfloat162*)lo)[2 * i + 1] = __nv_bfloat162(l2, l3);
}

// ---------------------------------------------------------------------------
// column sum of Wq — two-stage deterministic reduction
// ---------------------------------------------------------------------------
__global__ void colsum1_kernel(const float* __restrict__ W, float* __restrict__ part, int D) {
    int d = blockIdx.x * 256 + threadIdx.x;
    if (d >= D) return;
    int r0 = blockIdx.y * 128;
    float s = 0.f;
    for (int r = r0; r < r0 + 128; r++) s += W[(size_t)r * D + d];
    part[blockIdx.y * D + d] = s;
}
__global__ void colsum2_kernel(const float* __restrict__ part, float* __restrict__ wbar, int D) {
    int d = blockIdx.x * 256 + threadIdx.x;
    if (d >= D) return;
    float s = 0.f;
    #pragma unroll
    for (int i = 0; i < 8; i++) s += part[i * D + d];
    wbar[d] = s;
}

// ---------------------------------------------------------------------------
// per-row r[m] = sum / (sqrtD * norm)
// ---------------------------------------------------------------------------
__global__ void rowstat_kernel(const float* __restrict__ mk, float* __restrict__ r,
                               int M, int D, float sqrtD) {
    int warp = threadIdx.x >> 5, lane = threadIdx.x & 31;
    int m = blockIdx.x * 8 + warp;
    if (m >= M) return;
    const float* row = mk + (size_t)m * D;
    float s = 0.f, ss = 0.f;
    for (int j = lane * 4; j < D; j += 128) {
        float4 v = *(const float4*)(row + j);
        s  += v.x + v.y + v.z + v.w;
        ss += v.x * v.x + v.y * v.y + v.z * v.z + v.w * v.w;
    }
    #pragma unroll
    for (int off = 16; off; off >>= 1) {
        s  += __shfl_xor_sync(0xffffffffu, s, off);
        ss += __shfl_xor_sync(0xffffffffu, ss, off);
    }
    if (lane == 0) r[m] = s / (sqrtD * sqrtf(ss));
}

// ---------------------------------------------------------------------------
// sign(qm) per row
// ---------------------------------------------------------------------------
__global__ void qmsign_kernel(const float* __restrict__ x, const float* __restrict__ wbar,
                              int* __restrict__ sgn, int rows, int D) {
    int warp = threadIdx.x >> 5, lane = threadIdx.x & 31;
    int rn = blockIdx.x * 8 + warp;
    if (rn >= rows) return;
    const float* row = x + (size_t)rn * D;
    float s = 0.f;
    for (int j = lane * 4; j < D; j += 128) {
        float4 v = *(const float4*)(row + j);
        float4 w = *(const float4*)(wbar + j);
        s += v.x * w.x + v.y * w.y + v.z * w.z + v.w * w.w;
    }
    #pragma unroll
    for (int off = 16; off; off >>= 1) s += __shfl_xor_sync(0xffffffffu, s, off);
    if (lane == 0) sgn[rn] = (s >= 0.f) ? 1 : 0;
}

// ---------------------------------------------------------------------------
// topk: 2-stage bitonic. key = (orderable(value) << 32) | ~idx
// ---------------------------------------------------------------------------
__device__ __forceinline__ void bitonic_desc_1024(unsigned long long* s, int tid) {
    for (int k = 2; k <= 1024; k <<= 1) {
        for (int j = k >> 1; j > 0; j >>= 1) {
            int l = tid ^ j;
            if (l > tid) {
                unsigned long long a = s[tid], b = s[l];
                bool desc = ((tid & k) == 0);
                bool sw = desc ? (a < b) : (a > b);
                if (sw) { s[tid] = b; s[l] = a; }
            }
            __syncthreads();
        }
    }
}

__global__ void topk_stage1(const float* __restrict__ r, int M,
                            unsigned long long* __restrict__ cand) {
    int mode = blockIdx.y, seg = blockIdx.x, tid = threadIdx.x;
    __shared__ unsigned long long s[1024];
    int gi = seg * 1024 + tid;
    unsigned long long key = 0ull;
    if (gi < M) {
        uint32_t b = __float_as_uint(r[gi]);
        uint32_t u = (b & 0x80000000u) ? ~b : (b | 0x80000000u);
        if (mode) u = ~u;
        key = ((unsigned long long)u << 32) | (uint32_t)(~gi);
    }
    s[tid] = key;
    __syncthreads();
    bitonic_desc_1024(s, tid);
    if (tid < 32) cand[mode * 1024 + seg * 32 + tid] = s[tid];
}

__global__ void topk_stage2(const unsigned long long* __restrict__ cand, int ncand,
                            int* __restrict__ pos, int* __restrict__ neg) {
    int mode = blockIdx.x, tid = threadIdx.x;
    __shared__ unsigned long long s[1024];
    s[tid] = (tid < ncand) ? cand[mode * 1024 + tid] : 0ull;
    __syncthreads();
    bitonic_desc_1024(s, tid);
    if (tid < 32) {
        int idx = (int)(~(uint32_t)(s[tid] & 0xffffffffu));
        (mode ? neg : pos)[tid] = idx;
    }
}

// ---------------------------------------------------------------------------
// proj stage 1: K-split partials; grid (D/128, 4, KSPLIT); block 256
// ---------------------------------------------------------------------------
__global__ void __launch_bounds__(256) proj1_kernel(
        const float* __restrict__ mk, const float* __restrict__ mv,
        const float* __restrict__ Wk, const float* __restrict__ Wv,
        const int* __restrict__ pos, const int* __restrict__ neg,
        float* __restrict__ part, int D) {
    int mat = blockIdx.y, ksp = blockIdx.z;
    const float* src = (mat < 2) ? mk : mv;
    const float* W   = (mat < 2) ? Wk : Wv;
    const int*   idx = (mat & 1) ? neg : pos;
    float* outp = part + ((size_t)(mat * KSPLIT + ksp)) * TKK * D_MAX;

    int o0 = blockIdx.x * 128;
    int kbase = ksp * (1024 / KSPLIT);
    int kend  = kbase + (1024 / KSPLIT);
    __shared__ float Ks[32][36];
    __shared__ float Ws[32][132];
    __shared__ int   sidx[32];
    int tid = threadIdx.x;
    if (tid < 32) sidx[tid] = idx[tid];
    __syncthreads();

    int tx = tid & 31, ty = tid >> 5;
    float acc[4][4] = {};
    for (int k0 = kbase; k0 < kend; k0 += 32) {
        {
            int slot = tid >> 3; int d4 = (tid & 7) * 4;
            float4 v = *(const float4*)(src + (size_t)sidx[slot] * D + k0 + d4);
            Ks[d4 + 0][slot] = v.x; Ks[d4 + 1][slot] = v.y;
            Ks[d4 + 2][slot] = v.z; Ks[d4 + 3][slot] = v.w;
        }
        #pragma unroll
        for (int q = 0; q < 4; q++) {
            int l = tid + q * 256; int row = l >> 3; int d4 = (l & 7) * 4;
            float4 v = *(const float4*)(W + (size_t)(o0 + row) * D + k0 + d4);
            Ws[d4 + 0][row] = v.x; Ws[d4 + 1][row] = v.y;
            Ws[d4 + 2][row] = v.z; Ws[d4 + 3][row] = v.w;
        }
        __syncthreads();
        #pragma unroll
        for (int kk = 0; kk < 32; kk++) {
            float a[4], b[4];
            #pragma unroll
            for (int i = 0; i < 4; i++) a[i] = Ks[kk][ty * 4 + i];
            #pragma unroll
            for (int j = 0; j < 4; j++) b[j] = Ws[kk][tx * 4 + j];
            #pragma unroll
            for (int i = 0; i < 4; i++)
                #pragma unroll
                for (int j = 0; j < 4; j++) acc[i][j] += a[i] * b[j];
        }
        __syncthreads();
    }
    #pragma unroll
    for (int i = 0; i < 4; i++)
        #pragma unroll
        for (int j = 0; j < 4; j++)
            outp[(size_t)(ty * 4 + i) * D_MAX + o0 + tx * 4 + j] = acc[i][j];
}

// ---------------------------------------------------------------------------
// proj stage 2: combine KSPLIT partials (fixed order -> deterministic)
// ---------------------------------------------------------------------------
__global__ void proj2_kernel(const float* __restrict__ part,
                             float* __restrict__ Kp, float* __restrict__ Kn,
                             float* __restrict__ Vp, float* __restrict__ Vn, int D) {
    int idx = blockIdx.x * 256 + threadIdx.x;
    int mat = idx >> 15;
    int rem = idx & 32767;
    float s = 0.f;
    #pragma unroll
    for (int ksp = 0; ksp < KSPLIT; ksp++)
        s += part[((size_t)(mat * KSPLIT + ksp)) * TKK * D_MAX + rem];
    float* outm = (mat == 0) ? Kp : (mat == 1) ? Kn : (mat == 2) ? Vp : Vn;
    outm[rem] = s;
}

// ---------------------------------------------------------------------------
// HMMA bf16 split-precision GEMM (round-6 best config).
// ---------------------------------------------------------------------------
#define STR 80
#define OAhi 0
#define OAlo 10240
#define OBhi 20480
#define OBlo 30720
#define BUFB 40960
#define GEMM_DSMEM (3 * BUFB)

__global__ void __launch_bounds__(512) gemm_hmma_kernel(
        const __nv_bfloat16* __restrict__ Ahi, const __nv_bfloat16* __restrict__ Alo,
        const __nv_bfloat16* __restrict__ Bhi, const __nv_bfloat16* __restrict__ Blo,
        const float* __restrict__ bias, float* __restrict__ C, int Kd, int Nc) {
    extern __shared__ __align__(16) uint8_t dsm[];
    int tid = threadIdx.x, wid = tid >> 5, lane = tid & 31;
    int m0g = blockIdx.y * 128, n0g = blockIdx.x * 128;
    int m0w = (wid & 3) * 32, n0w = (wid >> 2) * 32;
    uint32_t sbase = smem_u32(dsm);
    uint32_t a_off = (lane % 16) * STR + (lane / 16) * 16;
    uint32_t b_off = ((lane & 7) + ((lane >> 4) << 3)) * STR + ((lane >> 3) & 1) * 16;
    float acc[2][4][4] = {};

    int nchunk = Kd / 32;
    int lrow = tid >> 2, lseg = tid & 3;
    uint32_t lso = lrow * STR + lseg * 16;
    auto load_chunk = [&](int c, int sel) {
        uint32_t bb = sbase + sel * BUFB;
        int k0 = c * 32;
        size_t ga = (size_t)(m0g + lrow) * Kd + k0 + lseg * 8;
        size_t gb = (size_t)(n0g + lrow) * Kd + k0 + lseg * 8;
        CP_ASYNC16(bb + OAhi + lso, Ahi + ga);
        CP_ASYNC16(bb + OAlo + lso, Alo + ga);
        CP_ASYNC16(bb + OBhi + lso, Bhi + gb);
        CP_ASYNC16(bb + OBlo + lso, Blo + gb);
    };

    load_chunk(0, 0); CP_COMMIT();
    load_chunk(1, 1); CP_COMMIT();

    for (int c = 0; c < nchunk; c++) {
        CP_WAIT(1);
        __syncthreads();
        if (c + 2 < nchunk) load_chunk(c + 2, (c + 2) % 3);
        CP_COMMIT();

        uint32_t bb = sbase + (c % 3) * BUFB;
        #pragma unroll
        for (int ks = 0; ks < 2; ks++) {
            uint32_t ahi[2][4], alo[2][4], bhi[2][4], blo[2][4];
            #pragma unroll
            for (int mf = 0; mf < 2; mf++) {
                uint32_t aaddr = bb + OAhi + (m0w + mf * 16) * STR + ks * 32 + a_off;
                ldsm_x4(ahi[mf], aaddr);
                ldsm_x4(alo[mf], aaddr + (OAlo - OAhi));
            }
            #pragma unroll
            for (int ng = 0; ng < 2; ng++) {
                uint32_t baddr = bb + OBhi + (n0w + ng * 16) * STR + ks * 32 + b_off;
                ldsm_x4(bhi[ng], baddr);
                ldsm_x4(blo[ng], baddr + (OBlo - OBhi));
            }
            #pragma unroll
            for (int mf = 0; mf < 2; mf++)
                #pragma unroll
                for (int nf = 0; nf < 4; nf++)
                    mma_bf16(acc[mf][nf], ahi[mf], &bhi[nf >> 1][(nf & 1) * 2]);
            #pragma unroll
            for (int mf = 0; mf < 2; mf++)
                #pragma unroll
                for (int nf = 0; nf < 4; nf++)
                    mma_bf16(acc[mf][nf], ahi[mf], &blo[nf >> 1][(nf & 1) * 2]);
            #pragma unroll
            for (int mf = 0; mf < 2; mf++)
                #pragma unroll
                for (int nf = 0; nf < 4; nf++)
                    mma_bf16(acc[mf][nf], alo[mf], &bhi[nf >> 1][(nf & 1) * 2]);
        }
    }

    #pragma unroll
    for (int mf = 0; mf < 2; mf++)
        #pragma unroll
        for (int nf = 0; nf < 4; nf++) {
            int col = n0g + n0w + nf * 8 + (lane & 3) * 2;
            float b0 = bias ? bias[col]     : 0.f;
            float b1 = bias ? bias[col + 1] : 0.f;
            int r0 = m0g + m0w + mf * 16 + (lane >> 2);
            float2 v0 = {acc[mf][nf][0] + b0, acc[mf][nf][1] + b1};
            float2 v1 = {acc[mf][nf][2] + b0, acc[mf][nf][3] + b1};
            *(float2*)(C + (size_t)r0 * Nc + col)       = v0;
            *(float2*)(C + (size_t)(r0 + 8) * Nc + col) = v1;
        }
}

// ---------------------------------------------------------------------------
// per-row attention (round-6/10 best); ctx emitted as bf16 hi/lo split
// ---------------------------------------------------------------------------
__global__ void __launch_bounds__(256) attn_kernel(
        const float* __restrict__ qfull,
        const float* __restrict__ Kp, const float* __restrict__ Kn,
        const float* __restrict__ Vp, const float* __restrict__ Vn,
        const int* __restrict__ pos, const int* __restrict__ neg,
        const int* __restrict__ sgn,
        __nv_bfloat16* __restrict__ ctxhi, __nv_bfloat16* __restrict__ ctxlo,
        float* __restrict__ avg_out, float* __restrict__ sel_out,
        int D, float scale) {
    int rn = blockIdx.x;
    int tid = threadIdx.x;
    int warp = tid >> 5, lane = tid & 31;
    __shared__ float qs[D_MAX];
    __shared__ float sc[NHEADS * TKK];

    int sg = sgn[rn];
    const float* Km = sg ? Kp : Kn;
    const float* Vm = sg ? Vp : Vn;
    const int* idx  = sg ? pos : neg;

    for (int j = tid * 4; j < D; j += 1024)
        *(float4*)(qs + j) = *(const float4*)(qfull + (size_t)rn * D + j);
    __syncthreads();

    for (int t = 0; t < 64; t++) {
        int p = warp * 64 + t;
        int h = p >> 5, k = p & 31;
        const float* kr = Km + (size_t)k * D + h * 64;
        const float* qr = qs + h * 64;
        float v = qr[lane] * kr[lane] + qr[lane + 32] * kr[lane + 32];
        #pragma unroll
        for (int off = 16; off; off >>= 1) v += __shfl_xor_sync(0xffffffffu, v, off);
        if (lane == 0) sc[p] = v * scale;
    }
    __syncthreads();

    #pragma unroll
    for (int hh = warp * 2; hh < warp * 2 + 2; hh++) {
        float v = sc[hh * 32 + lane];
        float mx = v;
        #pragma unroll
        for (int off = 16; off; off >>= 1) mx = fmaxf(mx, __shfl_xor_sync(0xffffffffu, mx, off));
        float e = expf(v - mx);
        float s = e;
        #pragma unroll
        for (int off = 16; off; off >>= 1) s += __shfl_xor_sync(0xffffffffu, s, off);
        sc[hh * 32 + lane] = e / s;
    }
    __syncthreads();

    if (tid < 32) {
        if (avg_out) {
            float a = 0.f;
            #pragma unroll
            for (int h = 0; h < NHEADS; h++) a += sc[h * 32 + tid];
            avg_out[(size_t)rn * TKK + tid] = a * (1.f / NHEADS);
        }
        if (sel_out) sel_out[(size_t)rn * TKK + tid] = (float)idx[tid];
    }

    for (int o = tid; o < D; o += 256) {
        int h = o >> 6;
        const float* arow = sc + h * 32;
        float a = 0.f;
        #pragma unroll
        for (int k = 0; k < TKK; k++) a += arow[k] * Vm[(size_t)k * D + o];
        __nv_bfloat16 hi = __float2bfloat16(a);
        __nv_bfloat16 lo = __float2bfloat16(a - __bfloat162float(hi));
        ctxhi[(size_t)rn * D + o] = hi;
        ctxlo[(size_t)rn * D + o] = lo;
    }
}

// ---------------------------------------------------------------------------
// LayerNorm in-place per row
// ---------------------------------------------------------------------------
__global__ void __launch_bounds__(256) ln_kernel(
        float* __restrict__ out, const float* __restrict__ gamma,
        const float* __restrict__ beta, int D, float eps) {
    int rn = blockIdx.x;
    float* row = out + (size_t)rn * D;
    int tid = threadIdx.x;
    int warp = tid >> 5, lane = tid & 31;
    __shared__ float ssum[8], ssq[8];

    float s = 0.f, ss = 0.f;
    for (int j = tid * 4; j < D; j += 1024) {
        float4 v = *(const float4*)(row + j);
        s  += v.x + v.y + v.z + v.w;
        ss += v.x * v.x + v.y * v.y + v.z * v.z + v.w * v.w;
    }
    #pragma unroll
    for (int off = 16; off; off >>= 1) {
        s  += __shfl_xor_sync(0xffffffffu, s, off);
        ss += __shfl_xor_sync(0xffffffffu, ss, off);
    }
    if (lane == 0) { ssum[warp] = s; ssq[warp] = ss; }
    __syncthreads();
    if (tid == 0) {
        float ts = 0.f, tq = 0.f;
        #pragma unroll
        for (int w = 0; w < 8; w++) { ts += ssum[w]; tq += ssq[w]; }
        ssum[0] = ts; ssq[0] = tq;
    }
    __syncthreads();
    float mu = ssum[0] / D;
    float var = ssq[0] / D - mu * mu;
    float rstd = rsqrtf(var + eps);
    for (int j = tid * 4; j < D; j += 1024) {
        float4 v = *(const float4*)(row + j);
        float4 g = *(const float4*)(gamma + j);
        float4 bb = *(const float4*)(beta + j);
        v.x = (v.x - mu) * rstd * g.x + bb.x;
        v.y = (v.y - mu) * rstd * g.y + bb.y;
        v.z = (v.z - mu) * rstd * g.z + bb.z;
        v.w = (v.w - mu) * rstd * g.w + bb.w;
        *(float4*)(row + j) = v;
    }
}

// ---------------------------------------------------------------------------
// launch — forked graph
// ---------------------------------------------------------------------------
extern "C" void kernel_launch(void* const* d_in, const int* in_sizes, int n_in,
                              void* d_out, int out_size) {
    const float* x     = (const float*)d_in[0];
    const float* mk    = (const float*)d_in[1];
    const float* mv    = (const float*)d_in[2];
    const float* Wq    = (const float*)d_in[3];
    const float* Wk    = (const float*)d_in[4];
    const float* Wv    = (const float*)d_in[5];
    const float* Wo    = (const float*)d_in[6];
    const float* bo    = (const float*)d_in[7];
    const float* gamma = (const float*)d_in[8];
    const float* beta  = (const float*)d_in[9];

    int D    = in_sizes[7];
    int rows = in_sizes[0] / D;           // B*N
    int M    = in_sizes[1] / D;
    int hd   = D / NHEADS;

    float* out = (float*)d_out;
    float* avg_out = nullptr;
    float* sel_out = nullptr;
    if ((long long)out_size >= (long long)rows * (D + 2 * TKK)) {
        avg_out = out + (size_t)rows * D;
        sel_out = avg_out + (size_t)rows * TKK;
    }

    float *p_r, *p_wbar, *p_part, *p_ppart, *p_Kp, *p_Kn, *p_Vp, *p_Vn, *p_qf;
    int *p_pos, *p_neg, *p_sgn;
    unsigned long long* p_cand;
    __nv_bfloat16 *p_xhi, *p_xlo, *p_chi, *p_clo, *p_Wqhi, *p_Wqlo, *p_Wohi, *p_Wolo;
    cudaGetSymbolAddress((void**)&p_r,    g_r);
    cudaGetSymbolAddress((void**)&p_wbar, g_wbar);
    cudaGetSymbolAddress((void**)&p_part, g_colpart);
    cudaGetSymbolAddress((void**)&p_ppart, g_projpart);
    cudaGetSymbolAddress((void**)&p_pos,  g_posidx);
    cudaGetSymbolAddress((void**)&p_neg,  g_negidx);
    cudaGetSymbolAddress((void**)&p_sgn,  g_sign);
    cudaGetSymbolAddress((void**)&p_cand, g_cand);
    cudaGetSymbolAddress((void**)&p_Kp,   g_Kp);
    cudaGetSymbolAddress((void**)&p_Kn,   g_Kn);
    cudaGetSymbolAddress((void**)&p_Vp,   g_Vp);
    cudaGetSymbolAddress((void**)&p_Vn,   g_Vn);
    cudaGetSymbolAddress((void**)&p_qf,   g_qfull);
    cudaGetSymbolAddress((void**)&p_xhi,  g_xhi);
    cudaGetSymbolAddress((void**)&p_xlo,  g_xlo);
    cudaGetSymbolAddress((void**)&p_chi,  g_ctxhi);
    cudaGetSymbolAddress((void**)&p_clo,  g_ctxlo);
    cudaGetSymbolAddress((void**)&p_Wqhi, g_Wqhi);
    cudaGetSymbolAddress((void**)&p_Wqlo, g_Wqlo);
    cudaGetSymbolAddress((void**)&p_Wohi, g_Wohi);
    cudaGetSymbolAddress((void**)&p_Wolo, g_Wolo);

    cudaFuncSetAttribute(gemm_hmma_kernel, cudaFuncAttributeMaxDynamicSharedMemorySize,
                         GEMM_DSMEM);

    static cudaStream_t sA = nullptr, sB = nullptr;
    static cudaEvent_t e0 = nullptr, eA = nullptr, eB = nullptr;
    if (!sA) {
        cudaStreamCreateWithFlags(&sA, cudaStreamNonBlocking);
        cudaStreamCreateWithFlags(&sB, cudaStreamNonBlocking);
        cudaEventCreateWithFlags(&e0, cudaEventDisableTiming);
        cudaEventCreateWithFlags(&eA, cudaEventDisableTiming);
        cudaEventCreateWithFlags(&eB, cudaEventDisableTiming);
    }

    float sqrtD = sqrtf((float)D);
    float scale = 1.f / sqrtf((float)hd);
    int nx4 = rows * D / 4, nw4 = D * D / 4;
    int segs = (M + 1023) / 1024;

    // ---- fork ----
    cudaEventRecord(e0, 0);
    cudaStreamWaitEvent(sA, e0, 0);
    cudaStreamWaitEvent(sB, e0, 0);

    // side A: rowstat -> topk -> proj1 -> proj2
    rowstat_kernel<<<(M + 7) / 8, 256, 0, sA>>>(mk, p_r, M, D, sqrtD);
    topk_stage1<<<dim3(segs, 2), 1024, 0, sA>>>(p_r, M, p_cand);
    topk_stage2<<<2, 1024, 0, sA>>>(p_cand, segs * 32, p_pos, p_neg);
    proj1_kernel<<<dim3(D / 128, 4, KSPLIT), 256, 0, sA>>>(mk, mv, Wk, Wv, p_pos, p_neg,
                                                           p_ppart, D);
    proj2_kernel<<<(4 * TKK * D_MAX) / 256, 256, 0, sA>>>(p_ppart, p_Kp, p_Kn,
                                                          p_Vp, p_Vn, D);
    cudaEventRecord(eA, sA);

    // side B: colsum -> qmsign, and Wo split (only needed before gemm2)
    colsum1_kernel<<<dim3((D + 255) / 256, 8), 256, 0, sB>>>(Wq, p_part, D);
    colsum2_kernel<<<(D + 255) / 256, 256, 0, sB>>>(p_part, p_wbar, D);
    qmsign_kernel<<<(rows + 7) / 8, 256, 0, sB>>>(x, p_wbar, p_sgn, rows, D);
    split_kernel<<<(nw4 + 255) / 256, 256, 0, sB>>>(Wo, p_Wohi, p_Wolo, nw4);
    cudaEventRecord(eB, sB);

    // main: x/Wq splits -> gemm1
    split_kernel<<<(nx4 + 255) / 256, 256>>>(x,  p_xhi,  p_xlo,  nx4);
    split_kernel<<<(nw4 + 255) / 256, 256>>>(Wq, p_Wqhi, p_Wqlo, nw4);
    gemm_hmma_kernel<<<dim3(D / 128, rows / 128), 512, GEMM_DSMEM>>>(
        p_xhi, p_xlo, p_Wqhi, p_Wqlo, nullptr, p_qf, D, D);

    // ---- join ----
    cudaStreamWaitEvent(0, eA, 0);
    cudaStreamWaitEvent(0, eB, 0);

    attn_kernel<<<rows, 256>>>(p_qf, p_Kp, p_Kn, p_Vp, p_Vn, p_pos, p_neg, p_sgn,
                               p_chi, p_clo, avg_out, sel_out, D, scale);

    gemm_hmma_kernel<<<dim3(D / 128, rows / 128), 512, GEMM_DSMEM>>>(
        p_chi, p_clo, p_Wohi, p_Wolo, bo, out, D, D);

    ln_kernel<<<rows, 256>>>(out, gamma, beta, D, 1e-5f);
}